// round 1
// baseline (speedup 1.0000x reference)
#include <cuda_runtime.h>
#include <cstdint>

// CharRNN on GB300 (sm_103a).
// Design: 128 blocks x 320 threads. Each block owns 8 batch rows.
// 10 warps = 10 RNN layers, software-pipelined as a wavefront over T:
//   warp for layer l computes timestep t = tick - l.
// Weights in registers (f32x2-packed), activations handed off through
// double-buffered shared memory, one __syncthreads per tick.
// Inner product uses Blackwell packed fma.rn.f32x2 (2 fp32 FMA / instr).

#define NBLK   128
#define NTHR   320
#define ROWS   8          // batch rows per block
#define TT     1024
#define LL     10
#define HID    32
#define VOC    256

typedef unsigned long long ull;

__device__ __forceinline__ void ffma2(ull &d, ull a, ull b) {
    asm("fma.rn.f32x2 %0, %1, %2, %0;" : "+l"(d) : "l"(a), "l"(b));
}

__device__ __forceinline__ float f2red(ull a) {
    float lo, hi;
    asm("mov.b64 {%0, %1}, %2;" : "=f"(lo), "=f"(hi) : "l"(a));
    return lo + hi;
}

// tanh(x) = 1 - 2/(exp(2x)+1).  __expf -> MUFU.EX2, __fdividef -> MUFU.RCP.
// Absolute error ~1e-6 (plenty vs 1e-3 final threshold); handles +/-inf sat.
__device__ __forceinline__ float tanh_fast(float x) {
    float e = __expf(2.0f * x);
    return 1.0f - __fdividef(2.0f, e + 1.0f);
}

__global__ void __launch_bounds__(NTHR, 1)
charrnn_kernel(const int*   __restrict__ x,      // [B, T]
               const float* __restrict__ emb,    // [VOC, 32]
               const float* __restrict__ W_ih,   // [L, 32, 32]
               const float* __restrict__ W_hh,   // [L, 32, 32]
               const float* __restrict__ b_ih,   // [L, 32]
               const float* __restrict__ b_hh,   // [L, 32]
               const float* __restrict__ W_fc,   // [VOC, 32]
               const float* __restrict__ b_fc,   // [VOC]
               float*       __restrict__ out)    // [B, VOC]
{
    __shared__ __align__(16) float sh[LL][2][ROWS][HID];   // layer outputs, double buffered
    __shared__ __align__(16) float sx[2][ROWS][HID];       // embedding input for layer 0

    const int tid  = threadIdx.x;
    const int wid  = tid >> 5;
    const int lane = tid & 31;
    const int row0 = blockIdx.x * ROWS;

    // Map warps to layers so layer 0 (which also does the embedding gather)
    // sits on an SMSP that only hosts 2 pipeline warps (10 warps -> 3/3/2/2).
    // smsp0 (w0,w4,w8) -> layers 4,5,6 ; smsp1 (w1,w5,w9) -> 7,8,9
    // smsp2 (w2,w6)    -> layers 0,1   ; smsp3 (w3,w7)    -> 2,3
    const int s = wid & 3;
    const int g = wid >> 2;
    const int base = (s == 0) ? 4 : (s == 1) ? 7 : (s == 2) ? 0 : 2;
    const int l = base + g;

    // ---- zero shared state (h(-1) = 0) ----
    {
        float* p = &sh[0][0][0][0];
        for (int i = tid; i < LL * 2 * ROWS * HID; i += NTHR) p[i] = 0.0f;
        float* q = &sx[0][0][0];
        for (int i = tid; i < 2 * ROWS * HID; i += NTHR) q[i] = 0.0f;
    }

    // ---- load this warp's layer weights into registers, f32x2-packed ----
    ull wih[16], whh[16];
    {
        const ulonglong2* p = (const ulonglong2*)(W_ih + (l * HID + lane) * HID);
        #pragma unroll
        for (int q = 0; q < 8; ++q) { ulonglong2 v = p[q]; wih[2*q] = v.x; wih[2*q+1] = v.y; }
        p = (const ulonglong2*)(W_hh + (l * HID + lane) * HID);
        #pragma unroll
        for (int q = 0; q < 8; ++q) { ulonglong2 v = p[q]; whh[2*q] = v.x; whh[2*q+1] = v.y; }
    }
    const float bias = __ldg(&b_ih[l * HID + lane]) + __ldg(&b_hh[l * HID + lane]);

    __syncthreads();

    // ---- preload embedding for t=0 into sx[0] ----
    if (l == 0) {
        #pragma unroll
        for (int r = 0; r < ROWS; ++r) {
            int idx = __ldg(&x[(row0 + r) * TT + 0]);
            sx[0][r][lane] = __ldg(&emb[idx * HID + lane]);
        }
    }

    // ---- pipelined mainloop: ticks u = 0 .. T+L-2 ----
    for (int u = 0; u < TT + LL - 1; ++u) {
        __syncthreads();

        // embedding prefetch for t = u+1 (layer-0 warp)
        if (l == 0) {
            const int t2 = u + 1;
            if (t2 < TT) {
                float* dst = &sx[t2 & 1][0][0];
                #pragma unroll
                for (int r = 0; r < ROWS; ++r) {
                    int idx = __ldg(&x[(row0 + r) * TT + t2]);
                    dst[r * HID + lane] = __ldg(&emb[idx * HID + lane]);
                }
            }
        }

        const int t = u - l;
        if ((unsigned)t < (unsigned)TT) {
            const int pin = t & 1;
            const float* inb = (l == 0) ? &sx[pin][0][0] : &sh[l - 1][pin][0][0];
            const float* hb  = &sh[l][(t - 1) & 1][0][0];
            float* ob        = &sh[l][pin][0][0];

            #pragma unroll
            for (int r = 0; r < ROWS; r += 2) {
                ull a0 = 0ull, a1 = 0ull;
                #pragma unroll
                for (int q = 0; q < 8; ++q) {
                    ulonglong2 va = *(const ulonglong2*)(inb + r * HID + q * 4);
                    ulonglong2 vb = *(const ulonglong2*)(inb + (r + 1) * HID + q * 4);
                    ffma2(a0, wih[2*q], va.x); ffma2(a0, wih[2*q+1], va.y);
                    ffma2(a1, wih[2*q], vb.x); ffma2(a1, wih[2*q+1], vb.y);
                }
                #pragma unroll
                for (int q = 0; q < 8; ++q) {
                    ulonglong2 va = *(const ulonglong2*)(hb + r * HID + q * 4);
                    ulonglong2 vb = *(const ulonglong2*)(hb + (r + 1) * HID + q * 4);
                    ffma2(a0, whh[2*q], va.x); ffma2(a0, whh[2*q+1], va.y);
                    ffma2(a1, whh[2*q], vb.x); ffma2(a1, whh[2*q+1], vb.y);
                }
                float s0 = f2red(a0) + bias;
                float s1 = f2red(a1) + bias;
                ob[r * HID + lane]       = tanh_fast(s0);
                ob[(r + 1) * HID + lane] = tanh_fast(s1);
            }
        }
    }

    __syncthreads();

    // ---- final FC: out[row] = h9(T-1) @ W_fc^T + b_fc ----
    // h9(1023) lives at parity (1023 & 1) = 1.
    const float* h9 = &sh[LL - 1][1][0][0];
    for (int i = tid; i < ROWS * VOC; i += NTHR) {
        const int r = i >> 8;
        const int v = i & (VOC - 1);
        const float4* w  = (const float4*)(W_fc + v * HID);
        const float4* hh = (const float4*)(h9 + r * HID);
        float sum = __ldg(&b_fc[v]);
        #pragma unroll
        for (int q = 0; q < 8; ++q) {
            float4 a = w[q], b = hh[q];
            sum += a.x * b.x + a.y * b.y + a.z * b.z + a.w * b.w;
        }
        out[(row0 + r) * VOC + v] = sum;
    }
}

extern "C" void kernel_launch(void* const* d_in, const int* in_sizes, int n_in,
                              void* d_out, int out_size)
{
    const int*   x    = (const int*)  d_in[0];
    const float* emb  = (const float*)d_in[1];
    const float* W_ih = (const float*)d_in[2];
    const float* W_hh = (const float*)d_in[3];
    const float* b_ih = (const float*)d_in[4];
    const float* b_hh = (const float*)d_in[5];
    const float* W_fc = (const float*)d_in[6];
    const float* b_fc = (const float*)d_in[7];
    float* out = (float*)d_out;

    charrnn_kernel<<<NBLK, NTHR>>>(x, emb, W_ih, W_hh, b_ih, b_hh, W_fc, b_fc, out);
}

// round 2
// speedup vs baseline: 1.1973x; 1.1973x over previous
#include <cuda_runtime.h>
#include <cstdint>

// CharRNN on GB300 (sm_103a), round 2.
// 128 blocks x 352 threads. Block owns 8 batch rows.
// Warps 0..9  = RNN layers (wavefront pipeline over T, 2 timesteps per tick).
// Warp 10     = embedding producer (LDG gather off the critical stages).
// Stage handoff through 4-deep shared buffers (row stride 36 floats: 16B-aligned,
// bank-rotated), synchronized with PAIRWISE named barriers (bar.sync id,64) —
// no block-wide __syncthreads in the mainloop.
// Each lane owns 2 output neurons (n, n+16) and 4 batch rows: every 16B LDS
// feeds 4 packed fma.rn.f32x2 (2 fp32 FMA each).

#define NBLK  128
#define NTHR  352
#define ROWS  8
#define TT    1024
#define LL    10
#define HID   32
#define VOC   256
#define LST   36                 // padded row stride in floats
#define NTICK (TT/2 + LL - 1)    // 521

typedef unsigned long long ull;

__device__ __forceinline__ void ffma2(ull &d, ull a, ull b) {
    asm("fma.rn.f32x2 %0, %1, %2, %0;" : "+l"(d) : "l"(a), "l"(b));
}
__device__ __forceinline__ float f2red(ull a) {
    float lo, hi;
    asm("mov.b64 {%0, %1}, %2;" : "=f"(lo), "=f"(hi) : "l"(a));
    return lo + hi;
}
// tanh(x) = 1 - 2/(exp(2x)+1); MUFU-based, abs err ~1e-6.
__device__ __forceinline__ float tanh_fast(float x) {
    float e = __expf(2.0f * x);
    return 1.0f - __fdividef(2.0f, e + 1.0f);
}
__device__ __forceinline__ void nbar(int id) {
    asm volatile("bar.sync %0, 64;" :: "r"(id) : "memory");
}

__global__ void __launch_bounds__(NTHR, 1)
charrnn_kernel(const int*   __restrict__ x,      // [B, T]
               const float* __restrict__ emb,    // [VOC, 32]
               const float* __restrict__ W_ih,   // [L, 32, 32]
               const float* __restrict__ W_hh,   // [L, 32, 32]
               const float* __restrict__ b_ih,   // [L, 32]
               const float* __restrict__ b_hh,   // [L, 32]
               const float* __restrict__ W_fc,   // [VOC, 32]
               const float* __restrict__ b_fc,   // [VOC]
               float*       __restrict__ out)    // [B, VOC]
{
    extern __shared__ float smem[];
    float* shl = smem;                         // [LL][4][ROWS][LST]
    float* sx  = smem + LL * 4 * ROWS * LST;   // [4][ROWS][LST]

    const int tid  = threadIdx.x;
    const int wid  = tid >> 5;
    const int lane = tid & 31;
    const int row0 = blockIdx.x * ROWS;

    // zero all buffers (h(-1) = 0; padding too)
    for (int i = tid; i < (LL * 4 + 4) * ROWS * LST; i += NTHR) smem[i] = 0.0f;

    const bool isProd = (wid == LL);
    const int  l    = wid;            // layer id for warps 0..9
    const int  half = lane >> 4;      // which 4-row group this lane handles
    const int  n0   = lane & 15;      // first owned output neuron
    const int  n1   = n0 + 16;        // second owned output neuron

    ull wih0[16], wih1[16], whh0[16], whh1[16];
    float bias0 = 0.0f, bias1 = 0.0f;
    if (!isProd) {
        const ulonglong2* p;
        p = (const ulonglong2*)(W_ih + (l * HID + n0) * HID);
        #pragma unroll
        for (int q = 0; q < 8; ++q) { ulonglong2 v = p[q]; wih0[2*q] = v.x; wih0[2*q+1] = v.y; }
        p = (const ulonglong2*)(W_ih + (l * HID + n1) * HID);
        #pragma unroll
        for (int q = 0; q < 8; ++q) { ulonglong2 v = p[q]; wih1[2*q] = v.x; wih1[2*q+1] = v.y; }
        p = (const ulonglong2*)(W_hh + (l * HID + n0) * HID);
        #pragma unroll
        for (int q = 0; q < 8; ++q) { ulonglong2 v = p[q]; whh0[2*q] = v.x; whh0[2*q+1] = v.y; }
        p = (const ulonglong2*)(W_hh + (l * HID + n1) * HID);
        #pragma unroll
        for (int q = 0; q < 8; ++q) { ulonglong2 v = p[q]; whh1[2*q] = v.x; whh1[2*q+1] = v.y; }
        bias0 = __ldg(&b_ih[l * HID + n0]) + __ldg(&b_hh[l * HID + n0]);
        bias1 = __ldg(&b_ih[l * HID + n1]) + __ldg(&b_hh[l * HID + n1]);
    }
    __syncthreads();

    // producer preload: embeddings for t = 0, 1 into sx slots 0, 1
    if (isProd) {
        int idxv = 0;
        if (lane < 16) {
            int r = lane & 7, s = lane >> 3;
            idxv = __ldg(&x[(row0 + r) * TT + s]);
        }
        #pragma unroll
        for (int k = 0; k < 16; ++k) {
            int idx = __shfl_sync(0xffffffffu, idxv, k);
            int r = k & 7, s = k >> 3;
            sx[(s & 3) * ROWS * LST + r * LST + lane] = __ldg(&emb[idx * HID + lane]);
        }
    }
    __syncthreads();

    if (isProd) {
        // ---- embedding producer: stage -1 of the wavefront ----
        for (int v = 0; v < NTICK; ++v) {
            const int t0 = 2 * v + 2;
            if (t0 < TT) {
                int idxv = 0;
                if (lane < 16) {
                    int r = lane & 7, s = lane >> 3;
                    idxv = __ldg(&x[(row0 + r) * TT + t0 + s]);
                }
                #pragma unroll
                for (int k = 0; k < 16; ++k) {
                    int idx = __shfl_sync(0xffffffffu, idxv, k);
                    int r = k & 7, s = k >> 3;
                    sx[((t0 + s) & 3) * ROWS * LST + r * LST + lane] =
                        __ldg(&emb[idx * HID + lane]);
                }
            }
            nbar(1);   // rendezvous with layer 0
        }
    } else {
        // ---- RNN layer warp: 2 timesteps per tick ----
        const float* base_in  = (l == 0) ? sx : (shl + (l - 1) * 4 * ROWS * LST);
        float*       base_own = shl + l * 4 * ROWS * LST;

        for (int v = 0; v < NTICK; ++v) {
            const int t0 = 2 * (v - l);
            if (t0 >= 0 && t0 < TT) {
                #pragma unroll
                for (int st = 0; st < 2; ++st) {
                    const int t = t0 + st;
                    const float* inb = base_in  + (t & 3) * ROWS * LST;
                    const float* hb  = base_own + ((t - 1) & 3) * ROWS * LST;
                    float*       ob  = base_own + (t & 3) * ROWS * LST;

                    ull acc0[4], acc1[4];
                    #pragma unroll
                    for (int r = 0; r < 4; ++r) { acc0[r] = 0ull; acc1[r] = 0ull; }

                    #pragma unroll
                    for (int r = 0; r < 4; ++r) {
                        const int rr = half * 4 + r;
                        #pragma unroll
                        for (int q = 0; q < 8; ++q) {
                            ulonglong2 va = *(const ulonglong2*)(inb + rr * LST + q * 4);
                            ffma2(acc0[r], wih0[2*q], va.x); ffma2(acc0[r], wih0[2*q+1], va.y);
                            ffma2(acc1[r], wih1[2*q], va.x); ffma2(acc1[r], wih1[2*q+1], va.y);
                        }
                        #pragma unroll
                        for (int q = 0; q < 8; ++q) {
                            ulonglong2 vh = *(const ulonglong2*)(hb + rr * LST + q * 4);
                            ffma2(acc0[r], whh0[2*q], vh.x); ffma2(acc0[r], whh0[2*q+1], vh.y);
                            ffma2(acc1[r], whh1[2*q], vh.x); ffma2(acc1[r], whh1[2*q+1], vh.y);
                        }
                    }
                    #pragma unroll
                    for (int r = 0; r < 4; ++r) {
                        const int rr = half * 4 + r;
                        ob[rr * LST + n0] = tanh_fast(f2red(acc0[r]) + bias0);
                        ob[rr * LST + n1] = tanh_fast(f2red(acc1[r]) + bias1);
                    }
                    __syncwarp();   // step-2 hh reads step-1 outputs across lanes
                }
            }
            nbar(l + 1);                 // rendezvous with upstream stage
            if (l < LL - 1) nbar(l + 2); // rendezvous with downstream stage
        }
    }

    __syncthreads();

    // ---- final FC: out = h9(1023) @ W_fc^T + b_fc ; h9(1023) in slot 3 ----
    const float* h9 = shl + ((LL - 1) * 4 + 3) * ROWS * LST;
    for (int i = tid; i < ROWS * VOC; i += NTHR) {
        const int r = i >> 8;
        const int v = i & (VOC - 1);
        const float4* w  = (const float4*)(W_fc + v * HID);
        const float*  hr = h9 + r * LST;
        float sum = __ldg(&b_fc[v]);
        #pragma unroll
        for (int q = 0; q < 8; ++q) {
            float4 a = w[q];
            sum += a.x * hr[q*4+0] + a.y * hr[q*4+1] + a.z * hr[q*4+2] + a.w * hr[q*4+3];
        }
        out[(row0 + r) * VOC + v] = sum;
    }
}

extern "C" void kernel_launch(void* const* d_in, const int* in_sizes, int n_in,
                              void* d_out, int out_size)
{
    const int*   x    = (const int*)  d_in[0];
    const float* emb  = (const float*)d_in[1];
    const float* W_ih = (const float*)d_in[2];
    const float* W_hh = (const float*)d_in[3];
    const float* b_ih = (const float*)d_in[4];
    const float* b_hh = (const float*)d_in[5];
    const float* W_fc = (const float*)d_in[6];
    const float* b_fc = (const float*)d_in[7];
    float* out = (float*)d_out;

    const int shbytes = (LL * 4 + 4) * ROWS * LST * (int)sizeof(float);  // 50688
    cudaFuncSetAttribute(charrnn_kernel,
                         cudaFuncAttributeMaxDynamicSharedMemorySize, shbytes);
    charrnn_kernel<<<NBLK, NTHR, shbytes>>>(x, emb, W_ih, W_hh, b_ih, b_hh,
                                            W_fc, b_fc, out);
}